// round 15
// baseline (speedup 1.0000x reference)
#include <cuda_runtime.h>
#include <cuda_fp16.h>
#include <math.h>

#define BATCH 256
#define MDIM  256
#define VDIM  1024
#define JITTER 1e-6f
#define RING_SLOTS 4

// ------------------------- device scratch (no allocs allowed) -------------------------
__device__ float  g_W  [(size_t)BATCH * MDIM * VDIM];   // 256 MB : W = L^{-1} A (fp32)
__device__ __half g_Wh [(size_t)BATCH * MDIM * VDIM];   // 128 MB : W in fp16 (iteration copy)
__device__ float  g_L  [(size_t)BATCH * MDIM * MDIM];   // 64 MB  : G, then L (lower)
__device__ float  g_Ldi[(size_t)BATCH * 4 * 64 * 64];   // 4 MB   : inv of diag 64x64 blocks of L
__device__ float  g_c  [(size_t)BATCH * MDIM];          // L^{-1} b

// ======================= K1: G = A A^T + jitter*I (3 lower 128x128 tiles) =======================
__global__ __launch_bounds__(256, 2) void syrk_kernel(const float* __restrict__ A)
{
    __shared__ float As[2][16][132];
    __shared__ float Bs[2][16][132];
    int t = blockIdx.x, b = blockIdx.y;
    int ti = (t == 0) ? 0 : 1;
    int tj = (t == 2) ? 1 : 0;

    const float* Abase = A + (size_t)b * (MDIM * VDIM);
    const float* Ai = Abase + (size_t)(ti * 128) * VDIM;
    const float* Aj = Abase + (size_t)(tj * 128) * VDIM;

    int tid = threadIdx.x;
    int tx = tid & 15, ty = tid >> 4;
    int lrow = tid >> 2, lf = tid & 3;

    float acc[8][8];
#pragma unroll
    for (int i = 0; i < 8; i++)
#pragma unroll
        for (int j = 0; j < 8; j++) acc[i][j] = 0.f;

    float4 pa0 = __ldcs((const float4*)&Ai[(size_t)lrow * VDIM + 4 * lf]);
    float4 pa1 = __ldcs((const float4*)&Ai[(size_t)(lrow + 64) * VDIM + 4 * lf]);
    float4 pb0 = __ldcs((const float4*)&Aj[(size_t)lrow * VDIM + 4 * lf]);
    float4 pb1 = __ldcs((const float4*)&Aj[(size_t)(lrow + 64) * VDIM + 4 * lf]);
    {
        float va[4] = {pa0.x, pa0.y, pa0.z, pa0.w};
        float vb[4] = {pa1.x, pa1.y, pa1.z, pa1.w};
        float vc[4] = {pb0.x, pb0.y, pb0.z, pb0.w};
        float vd[4] = {pb1.x, pb1.y, pb1.z, pb1.w};
#pragma unroll
        for (int c = 0; c < 4; c++) {
            As[0][4 * lf + c][lrow]      = va[c];
            As[0][4 * lf + c][lrow + 64] = vb[c];
            Bs[0][4 * lf + c][lrow]      = vc[c];
            Bs[0][4 * lf + c][lrow + 64] = vd[c];
        }
    }
    __syncthreads();

    int buf = 0;
    for (int kt = 0; kt < 64; kt++) {
        if (kt < 63) {
            int k0 = (kt + 1) * 16;
            pa0 = __ldcs((const float4*)&Ai[(size_t)lrow * VDIM + k0 + 4 * lf]);
            pa1 = __ldcs((const float4*)&Ai[(size_t)(lrow + 64) * VDIM + k0 + 4 * lf]);
            pb0 = __ldcs((const float4*)&Aj[(size_t)lrow * VDIM + k0 + 4 * lf]);
            pb1 = __ldcs((const float4*)&Aj[(size_t)(lrow + 64) * VDIM + k0 + 4 * lf]);
        }
#pragma unroll
        for (int kk = 0; kk < 16; kk++) {
            float4 alo = *(const float4*)&As[buf][kk][4 * ty];
            float4 ahi = *(const float4*)&As[buf][kk][64 + 4 * ty];
            float4 blo = *(const float4*)&Bs[buf][kk][4 * tx];
            float4 bhi = *(const float4*)&Bs[buf][kk][64 + 4 * tx];
            float ar[8] = {alo.x, alo.y, alo.z, alo.w, ahi.x, ahi.y, ahi.z, ahi.w};
            float br[8] = {blo.x, blo.y, blo.z, blo.w, bhi.x, bhi.y, bhi.z, bhi.w};
#pragma unroll
            for (int i = 0; i < 8; i++)
#pragma unroll
                for (int j = 0; j < 8; j++) acc[i][j] = fmaf(ar[i], br[j], acc[i][j]);
        }
        if (kt < 63) {
            int nb = buf ^ 1;
            float va[4] = {pa0.x, pa0.y, pa0.z, pa0.w};
            float vb[4] = {pa1.x, pa1.y, pa1.z, pa1.w};
            float vc[4] = {pb0.x, pb0.y, pb0.z, pb0.w};
            float vd[4] = {pb1.x, pb1.y, pb1.z, pb1.w};
#pragma unroll
            for (int c = 0; c < 4; c++) {
                As[nb][4 * lf + c][lrow]      = va[c];
                As[nb][4 * lf + c][lrow + 64] = vb[c];
                Bs[nb][4 * lf + c][lrow]      = vc[c];
                Bs[nb][4 * lf + c][lrow + 64] = vd[c];
            }
            __syncthreads();
            buf = nb;
        }
    }

    float* Gb = g_L + (size_t)b * (MDIM * MDIM);
#pragma unroll
    for (int rr = 0; rr < 8; rr++) {
        int rloc = (rr < 4) ? (4 * ty + rr) : (64 + 4 * ty + rr - 4);
        int grow = ti * 128 + rloc;
#pragma unroll
        for (int q = 0; q < 2; q++) {
            int cloc = 4 * tx + 64 * q;
            float4 v = make_float4(acc[rr][4 * q + 0], acc[rr][4 * q + 1],
                                   acc[rr][4 * q + 2], acc[rr][4 * q + 3]);
            if (ti == tj) {
                int d = rloc - cloc;
                if (d >= 0 && d < 4) ((float*)&v)[d] += JITTER;
            }
            *(float4*)&Gb[(size_t)grow * MDIM + tj * 128 + cloc] = v;
        }
    }
}

// ====== K2: per-batch Cholesky in packed SMEM + diag-block inverses + c = L^{-1} b ======
#define PIDX(i, j) ((i) * ((i) + 1) / 2 + (j))
__global__ __launch_bounds__(256) void chol_kernel(const float* __restrict__ b_in)
{
    extern __shared__ float sm2[];
    float* P    = sm2;
    float* Inv  = sm2 + 32896;
    float* tst  = Inv + 4 * 64 * 65;
    float* cvec = tst + 64;
    float* colk = cvec + 256;

    int b = blockIdx.x, tid = threadIdx.x;
    int w = tid >> 5, lane = tid & 31;
    const float* Gb = g_L + (size_t)b * (MDIM * MDIM);

    {
        int i = tid, base = PIDX(i, 0);
        for (int j = 0; j <= i; j++) P[base + j] = Gb[i * MDIM + j];
    }
    __syncthreads();

    for (int k = 0; k < MDIM; k++) {
        if (tid == 0) P[PIDX(k, k)] = sqrtf(P[PIDX(k, k)]);
        __syncthreads();
        float dk = P[PIDX(k, k)];
        if (tid > k) {
            float v = P[PIDX(tid, 0) + k] / dk;
            P[PIDX(tid, 0) + k] = v;
            colk[tid] = v;
        }
        __syncthreads();
        for (int i = k + 1 + w; i < MDIM; i += 8) {
            float lik = colk[i];
            int base = PIDX(i, 0);
            for (int j = k + 1 + lane; j <= i; j += 32)
                P[base + j] = fmaf(-lik, colk[j], P[base + j]);
        }
        __syncthreads();
    }

    {
        int blk = tid >> 6, col = tid & 63, b0 = blk * 64;
        float* Ib = Inv + blk * 64 * 65;
        for (int i = 0; i < col; i++) Ib[i * 65 + col] = 0.f;
        for (int i = col; i < 64; i++) {
            int gi = b0 + i, gbase = PIDX(gi, 0);
            float s = (i == col) ? 1.f : 0.f;
            for (int k = col; k < i; k++) s = fmaf(-P[gbase + b0 + k], Ib[k * 65 + col], s);
            Ib[i * 65 + col] = s / P[gbase + gi];
        }
    }
    __syncthreads();

    {
        const float* bv = b_in + (size_t)b * MDIM;
        for (int blk = 0; blk < 4; blk++) {
            if (tid < 64) {
                int gi = blk * 64 + tid, gb = PIDX(gi, 0);
                float s = bv[gi];
                for (int j = 0; j < blk * 64; j++) s = fmaf(-P[gb + j], cvec[j], s);
                tst[tid] = s;
            }
            __syncthreads();
            if (tid < 64) {
                const float* Ib = Inv + blk * 64 * 65 + tid * 65;
                float s = 0.f;
                for (int k = 0; k < 64; k++) s = fmaf(Ib[k], tst[k], s);
                cvec[blk * 64 + tid] = s;
            }
            __syncthreads();
        }
    }

    {
        int i = tid, base = PIDX(i, 0);
        float* Lo = g_L + (size_t)b * (MDIM * MDIM) + i * MDIM;
        for (int j = 0; j <= i; j++) Lo[j] = P[base + j];

        int blk = tid >> 6, r = tid & 63;
        const float* Ib = Inv + blk * 64 * 65 + r * 65;
        float* o = g_Ldi + (((size_t)b * 4 + blk) * 64 + r) * 64;
        for (int k = 0; k < 64; k++) o[k] = Ib[k];

        g_c[(size_t)b * MDIM + tid] = cvec[tid];
    }
}

// =================== K3: W = L^{-1} A  (blocked trsm; writes fp32 + fp16 copies) ===================
__global__ __launch_bounds__(256, 2) void trsm_kernel(const float* __restrict__ A)
{
    extern __shared__ float sm3[];
    float* Tp = sm3;             // [64][132]
    float* Lb = sm3 + 8448;      // [2][16][68]
    float* Wt = Lb + 2176;       // [2][16][132]
    float* Db = sm3 + 8448;      // [64][68]  (overlaps Lb/Wt)

    int vt = blockIdx.x, b = blockIdx.y;
    int vc = vt * 128;
    int tid = threadIdx.x, tx = tid & 15, ty = tid >> 4;
    const float* Ab = A + (size_t)b * (MDIM * VDIM);
    const float* Lg = g_L + (size_t)b * (MDIM * MDIM);
    float* Wg = g_W + (size_t)b * (MDIM * VDIM);
    __half* Wh = g_Wh + (size_t)b * (MDIM * VDIM);

    int r4 = tid >> 2, f4 = tid & 3;
    int kkA = tid >> 5, cg = tid & 31;

    for (int i = 0; i < 4; i++) {
        float acc[4][8];
#pragma unroll
        for (int r = 0; r < 4; r++)
#pragma unroll
            for (int q = 0; q < 2; q++) {
                float4 av = __ldcs((const float4*)&Ab[(size_t)(i * 64 + 4 * ty + r) * VDIM + vc + 4 * tx + 64 * q]);
                acc[r][4 * q + 0] = av.x; acc[r][4 * q + 1] = av.y;
                acc[r][4 * q + 2] = av.z; acc[r][4 * q + 3] = av.w;
            }

        int nkt = 4 * i;
        if (nkt > 0) {
            float4 lv  = *(const float4*)&Lg[(size_t)(i * 64 + r4) * MDIM + 4 * f4];
            float4 wv0 = *(const float4*)&Wg[(size_t)(kkA)     * VDIM + vc + 4 * cg];
            float4 wv1 = *(const float4*)&Wg[(size_t)(kkA + 8) * VDIM + vc + 4 * cg];
            Lb[(4 * f4 + 0) * 68 + r4] = lv.x; Lb[(4 * f4 + 1) * 68 + r4] = lv.y;
            Lb[(4 * f4 + 2) * 68 + r4] = lv.z; Lb[(4 * f4 + 3) * 68 + r4] = lv.w;
            *(float4*)&Wt[kkA * 132 + 4 * cg] = wv0;
            *(float4*)&Wt[(kkA + 8) * 132 + 4 * cg] = wv1;
            __syncthreads();

            int buf = 0;
            for (int kt = 0; kt < nkt; kt++) {
                float4 lvn, wv0n, wv1n;
                if (kt + 1 < nkt) {
                    int k0 = (kt + 1) * 16;
                    lvn  = *(const float4*)&Lg[(size_t)(i * 64 + r4) * MDIM + k0 + 4 * f4];
                    wv0n = *(const float4*)&Wg[(size_t)(k0 + kkA)     * VDIM + vc + 4 * cg];
                    wv1n = *(const float4*)&Wg[(size_t)(k0 + kkA + 8) * VDIM + vc + 4 * cg];
                }
                const float* Lc = Lb + buf * 1088;
                const float* Wc = Wt + buf * 2112;
#pragma unroll
                for (int kk = 0; kk < 16; kk++) {
                    float4 a4 = *(const float4*)&Lc[kk * 68 + 4 * ty];
                    float4 w0 = *(const float4*)&Wc[kk * 132 + 4 * tx];
                    float4 w1 = *(const float4*)&Wc[kk * 132 + 64 + 4 * tx];
                    float ar[4] = {a4.x, a4.y, a4.z, a4.w};
                    float wv[8] = {w0.x, w0.y, w0.z, w0.w, w1.x, w1.y, w1.z, w1.w};
#pragma unroll
                    for (int r = 0; r < 4; r++)
#pragma unroll
                        for (int c = 0; c < 8; c++) acc[r][c] = fmaf(-ar[r], wv[c], acc[r][c]);
                }
                if (kt + 1 < nkt) {
                    int nb = buf ^ 1;
                    float* Ln = Lb + nb * 1088;
                    float* Wn = Wt + nb * 2112;
                    Ln[(4 * f4 + 0) * 68 + r4] = lvn.x; Ln[(4 * f4 + 1) * 68 + r4] = lvn.y;
                    Ln[(4 * f4 + 2) * 68 + r4] = lvn.z; Ln[(4 * f4 + 3) * 68 + r4] = lvn.w;
                    *(float4*)&Wn[kkA * 132 + 4 * cg] = wv0n;
                    *(float4*)&Wn[(kkA + 8) * 132 + 4 * cg] = wv1n;
                    __syncthreads();
                    buf = nb;
                }
            }
            __syncthreads();
        }

#pragma unroll
        for (int r = 0; r < 4; r++)
#pragma unroll
            for (int q = 0; q < 2; q++) {
                float4 o = make_float4(acc[r][4 * q + 0], acc[r][4 * q + 1],
                                       acc[r][4 * q + 2], acc[r][4 * q + 3]);
                *(float4*)&Tp[(4 * ty + r) * 132 + 4 * tx + 64 * q] = o;
            }
#pragma unroll
        for (int s = 0; s < 4; s++) {
            int n = tid + 256 * s;
            int r = n >> 4, f = n & 15;
            float4 dv = *(const float4*)&g_Ldi[(((size_t)b * 4 + i) * 64 + r) * 64 + 4 * f];
            Db[(4 * f + 0) * 68 + r] = dv.x; Db[(4 * f + 1) * 68 + r] = dv.y;
            Db[(4 * f + 2) * 68 + r] = dv.z; Db[(4 * f + 3) * 68 + r] = dv.w;
        }
        __syncthreads();

        float acc2[4][8];
#pragma unroll
        for (int r = 0; r < 4; r++)
#pragma unroll
            for (int c = 0; c < 8; c++) acc2[r][c] = 0.f;
#pragma unroll 16
        for (int kk = 0; kk < 64; kk++) {
            float4 a4 = *(const float4*)&Db[kk * 68 + 4 * ty];
            float4 t0 = *(const float4*)&Tp[kk * 132 + 4 * tx];
            float4 t1 = *(const float4*)&Tp[kk * 132 + 64 + 4 * tx];
            float ar[4] = {a4.x, a4.y, a4.z, a4.w};
            float tv[8] = {t0.x, t0.y, t0.z, t0.w, t1.x, t1.y, t1.z, t1.w};
#pragma unroll
            for (int r = 0; r < 4; r++)
#pragma unroll
                for (int c = 0; c < 8; c++) acc2[r][c] = fmaf(ar[r], tv[c], acc2[r][c]);
        }

#pragma unroll
        for (int r = 0; r < 4; r++)
#pragma unroll
            for (int q = 0; q < 2; q++) {
                float4 o = make_float4(acc2[r][4 * q + 0], acc2[r][4 * q + 1],
                                       acc2[r][4 * q + 2], acc2[r][4 * q + 3]);
                size_t off = (size_t)(i * 64 + 4 * ty + r) * VDIM + vc + 4 * tx + 64 * q;
                *(float4*)&Wg[off] = o;
                __half2 h01 = __floats2half2_rn(o.x, o.y);
                __half2 h23 = __floats2half2_rn(o.z, o.w);
                __half2 hh[2] = {h01, h23};
                *(uint2*)&Wh[off] = *(uint2*)hh;
            }
        __syncthreads();
    }
}

// =================== K5: fused ADMM loop (cp.async ring pipeline on fp16 W) ===================
__device__ __forceinline__ void cp_async16(void* smem_dst, const void* gmem_src)
{
    unsigned dst = (unsigned)__cvta_generic_to_shared(smem_dst);
    asm volatile("cp.async.cg.shared.global [%0], [%1], 16;"
                 :: "r"(dst), "l"(gmem_src) : "memory");
}

__global__ __launch_bounds__(256, 2) void admm_kernel(
    const float* __restrict__ x_in, const int* __restrict__ mask,
    float* __restrict__ out)
{
    extern __shared__ __align__(16) unsigned char smraw[];
    float* rsh = (float*)smraw;
    float* vp  = rsh + 1024;
    float* cc  = rsh + 9216;
    __half* ring = (__half*)(smraw + 37888);

    int b = blockIdx.x, tid = threadIdx.x;
    int w = tid >> 5, lane = tid & 31;
    const __half* Whb = g_Wh + (size_t)b * (MDIM * VDIM);
    const float*  Wfb = g_W  + (size_t)b * (MDIM * VDIM);
    __half* ringw = ring + w * (RING_SLOTS * 1024);

#pragma unroll
    for (int r = 0; r < 3; r++) {
        const __half* grow = Whb + (size_t)(w * 32 + r) * VDIM;
        __half* slot = ringw + r * 1024;
#pragma unroll
        for (int q = 0; q < 4; q++) {
            int ch = lane + 32 * q;
            cp_async16(slot + ch * 8, grow + ch * 8);
        }
        asm volatile("cp.async.commit_group;" ::: "memory");
    }

    float4 xreg = *(const float4*)&x_in[(size_t)b * VDIM + 4 * tid];
    int4 m4 = *(const int4*)&mask[4 * tid];
    float4 ureg = make_float4(0.f, 0.f, 0.f, 0.f);
    float4 rown = xreg;
    cc[tid] = g_c[(size_t)b * MDIM + tid];
    *(float4*)&rsh[4 * tid] = xreg;

    for (int it = 0; it < 100; it++) {
        __syncthreads();
        float rr[32];
#pragma unroll
        for (int q = 0; q < 4; q++) {
            float4 r0 = *(float4*)&rsh[256 * q + 8 * lane];
            float4 r1 = *(float4*)&rsh[256 * q + 8 * lane + 4];
            rr[8 * q + 0] = r0.x; rr[8 * q + 1] = r0.y; rr[8 * q + 2] = r0.z; rr[8 * q + 3] = r0.w;
            rr[8 * q + 4] = r1.x; rr[8 * q + 5] = r1.y; rr[8 * q + 6] = r1.z; rr[8 * q + 7] = r1.w;
        }
        float v[32];
#pragma unroll
        for (int c = 0; c < 32; c++) v[c] = 0.f;

        for (int j = 0; j < 32; j++) {
            {
                int pr = (j + 3) & 31;
                const __half* grow = Whb + (size_t)(w * 32 + pr) * VDIM;
                __half* slot = ringw + ((j + 3) & 3) * 1024;
#pragma unroll
                for (int q = 0; q < 4; q++) {
                    int ch = lane + 32 * q;
                    cp_async16(slot + ch * 8, grow + ch * 8);
                }
                asm volatile("cp.async.commit_group;" ::: "memory");
            }
            asm volatile("cp.async.wait_group 3;" ::: "memory");

            const __half* slot = ringw + (j & 3) * 1024;
            float s = 0.f;
#pragma unroll
            for (int q = 0; q < 4; q++) {
                uint4 u = *(const uint4*)(slot + (lane + 32 * q) * 8);
                float2 f0 = __half22float2(*(__half2*)&u.x);
                float2 f1 = __half22float2(*(__half2*)&u.y);
                float2 f2 = __half22float2(*(__half2*)&u.z);
                float2 f3 = __half22float2(*(__half2*)&u.w);
                s = fmaf(f0.x, rr[8 * q + 0], s); s = fmaf(f0.y, rr[8 * q + 1], s);
                s = fmaf(f1.x, rr[8 * q + 2], s); s = fmaf(f1.y, rr[8 * q + 3], s);
                s = fmaf(f2.x, rr[8 * q + 4], s); s = fmaf(f2.y, rr[8 * q + 5], s);
                s = fmaf(f3.x, rr[8 * q + 6], s); s = fmaf(f3.y, rr[8 * q + 7], s);
            }
#pragma unroll
            for (int off = 16; off > 0; off >>= 1) s += __shfl_xor_sync(0xffffffffu, s, off);
            float coef = 0.5f * s - cc[(w << 5) + j];
#pragma unroll
            for (int q = 0; q < 4; q++) {
                uint4 u = *(const uint4*)(slot + (lane + 32 * q) * 8);
                float2 f0 = __half22float2(*(__half2*)&u.x);
                float2 f1 = __half22float2(*(__half2*)&u.y);
                float2 f2 = __half22float2(*(__half2*)&u.z);
                float2 f3 = __half22float2(*(__half2*)&u.w);
                v[8 * q + 0] = fmaf(coef, f0.x, v[8 * q + 0]); v[8 * q + 1] = fmaf(coef, f0.y, v[8 * q + 1]);
                v[8 * q + 2] = fmaf(coef, f1.x, v[8 * q + 2]); v[8 * q + 3] = fmaf(coef, f1.y, v[8 * q + 3]);
                v[8 * q + 4] = fmaf(coef, f2.x, v[8 * q + 4]); v[8 * q + 5] = fmaf(coef, f2.y, v[8 * q + 5]);
                v[8 * q + 6] = fmaf(coef, f3.x, v[8 * q + 6]); v[8 * q + 7] = fmaf(coef, f3.y, v[8 * q + 7]);
            }
        }
#pragma unroll
        for (int q = 0; q < 4; q++) {
            *(float4*)&vp[w * 1024 + 256 * q + 8 * lane]     = make_float4(v[8 * q + 0], v[8 * q + 1], v[8 * q + 2], v[8 * q + 3]);
            *(float4*)&vp[w * 1024 + 256 * q + 8 * lane + 4] = make_float4(v[8 * q + 4], v[8 * q + 5], v[8 * q + 6], v[8 * q + 7]);
        }
        __syncthreads();

        float4 vs = make_float4(0.f, 0.f, 0.f, 0.f);
#pragma unroll
        for (int ww = 0; ww < 8; ww++) {
            float4 p = *(float4*)&vp[ww * 1024 + 4 * tid];
            vs.x += p.x; vs.y += p.y; vs.z += p.z; vs.w += p.w;
        }
        float4 xk;
        xk.x = 0.5f * rown.x - vs.x;
        xk.y = 0.5f * rown.y - vs.y;
        xk.z = 0.5f * rown.z - vs.z;
        xk.w = 0.5f * rown.w - vs.w;

        float wv, zv;
        wv = xk.x + ureg.x; zv = (m4.x > 0) ? fminf(wv, 0.f) : wv; ureg.x = wv - zv; rown.x = xreg.x + zv - ureg.x;
        wv = xk.y + ureg.y; zv = (m4.y > 0) ? fminf(wv, 0.f) : wv; ureg.y = wv - zv; rown.y = xreg.y + zv - ureg.y;
        wv = xk.z + ureg.z; zv = (m4.z > 0) ? fminf(wv, 0.f) : wv; ureg.z = wv - zv; rown.z = xreg.z + zv - ureg.z;
        wv = xk.w + ureg.w; zv = (m4.w > 0) ? fminf(wv, 0.f) : wv; ureg.w = wv - zv; rown.w = xreg.w + zv - ureg.w;
        *(float4*)&rsh[4 * tid] = rown;
    }

    asm volatile("cp.async.wait_group 0;" ::: "memory");

    __syncthreads();
    {
        float rr[32];
#pragma unroll
        for (int q = 0; q < 4; q++) {
            float4 r0 = *(float4*)&rsh[256 * q + 8 * lane];
            float4 r1 = *(float4*)&rsh[256 * q + 8 * lane + 4];
            rr[8 * q + 0] = r0.x; rr[8 * q + 1] = r0.y; rr[8 * q + 2] = r0.z; rr[8 * q + 3] = r0.w;
            rr[8 * q + 4] = r1.x; rr[8 * q + 5] = r1.y; rr[8 * q + 6] = r1.z; rr[8 * q + 7] = r1.w;
        }
        float v[32];
#pragma unroll
        for (int c = 0; c < 32; c++) v[c] = 0.f;

        for (int j = 0; j < 32; j++) {
            int m = (w << 5) + j;
            const float4* row = (const float4*)(Wfb + (size_t)m * VDIM);
            float af[32];
#pragma unroll
            for (int q = 0; q < 4; q++) {
                float4 a0 = __ldcs(&row[2 * (lane + 32 * q)]);
                float4 a1 = __ldcs(&row[2 * (lane + 32 * q) + 1]);
                af[8 * q + 0] = a0.x; af[8 * q + 1] = a0.y; af[8 * q + 2] = a0.z; af[8 * q + 3] = a0.w;
                af[8 * q + 4] = a1.x; af[8 * q + 5] = a1.y; af[8 * q + 6] = a1.z; af[8 * q + 7] = a1.w;
            }
            float s = 0.f;
#pragma unroll
            for (int c = 0; c < 32; c++) s = fmaf(af[c], rr[c], s);
#pragma unroll
            for (int off = 16; off > 0; off >>= 1) s += __shfl_xor_sync(0xffffffffu, s, off);
            float coef = 0.5f * s - cc[m];
#pragma unroll
            for (int c = 0; c < 32; c++) v[c] = fmaf(coef, af[c], v[c]);
        }
#pragma unroll
        for (int q = 0; q < 4; q++) {
            *(float4*)&vp[w * 1024 + 256 * q + 8 * lane]     = make_float4(v[8 * q + 0], v[8 * q + 1], v[8 * q + 2], v[8 * q + 3]);
            *(float4*)&vp[w * 1024 + 256 * q + 8 * lane + 4] = make_float4(v[8 * q + 4], v[8 * q + 5], v[8 * q + 6], v[8 * q + 7]);
        }
        __syncthreads();

        float4 vs = make_float4(0.f, 0.f, 0.f, 0.f);
#pragma unroll
        for (int ww = 0; ww < 8; ww++) {
            float4 p = *(float4*)&vp[ww * 1024 + 4 * tid];
            vs.x += p.x; vs.y += p.y; vs.z += p.z; vs.w += p.w;
        }
        float4 xk;
        xk.x = 0.5f * rown.x - vs.x;
        xk.y = 0.5f * rown.y - vs.y;
        xk.z = 0.5f * rown.z - vs.z;
        xk.w = 0.5f * rown.w - vs.w;
        *(float4*)&out[(size_t)b * VDIM + 4 * tid] = xk;
    }
}

// ======================================= launch =======================================
extern "C" void kernel_launch(void* const* d_in, const int* in_sizes, int n_in,
                              void* d_out, int out_size)
{
    (void)in_sizes; (void)n_in; (void)out_size;
    const float* x    = (const float*)d_in[0];
    const float* bvec = (const float*)d_in[1];
    const float* A    = (const float*)d_in[2];
    const int*   mask = (const int*)d_in[3];
    float* out = (float*)d_out;

    size_t chol_smem = (size_t)(32896 + 4 * 64 * 65 + 64 + 256 + 256) * sizeof(float);
    size_t trsm_smem = (size_t)(8448 + 2176 + 4224) * sizeof(float);
    size_t admm_smem = (size_t)37888 + (size_t)8 * RING_SLOTS * 1024 * sizeof(__half);

    cudaFuncSetAttribute((const void*)chol_kernel, cudaFuncAttributeMaxDynamicSharedMemorySize, (int)chol_smem);
    cudaFuncSetAttribute((const void*)trsm_kernel, cudaFuncAttributeMaxDynamicSharedMemorySize, (int)trsm_smem);
    cudaFuncSetAttribute((const void*)admm_kernel, cudaFuncAttributeMaxDynamicSharedMemorySize, (int)admm_smem);

    syrk_kernel<<<dim3(3, BATCH), 256>>>(A);
    chol_kernel<<<BATCH, 256, chol_smem>>>(bvec);
    trsm_kernel<<<dim3(8, BATCH), 256, trsm_smem>>>(A);
    admm_kernel<<<BATCH, 256, admm_smem>>>(x, mask, out);
}

// round 17
// speedup vs baseline: 1.0036x; 1.0036x over previous
#include <cuda_runtime.h>
#include <cuda_fp16.h>
#include <math.h>

#define BATCH 256
#define MDIM  256
#define VDIM  1024
#define JITTER 1e-6f
#define RING_SLOTS 4

// ------------------------- device scratch (no allocs allowed) -------------------------
__device__ float  g_W  [(size_t)BATCH * MDIM * VDIM];   // 256 MB : W = L^{-1} A (fp32)
__device__ __half g_Wh [(size_t)BATCH * MDIM * VDIM];   // 128 MB : W in fp16 (iteration copy)
__device__ float  g_L  [(size_t)BATCH * MDIM * MDIM];   // 64 MB  : G, then L (lower)
__device__ float  g_Ldi[(size_t)BATCH * 4 * 64 * 64];   // 4 MB   : inv of diag 64x64 blocks of L
__device__ float  g_c  [(size_t)BATCH * MDIM];          // L^{-1} b

// ======================= K1: G = A A^T + jitter*I (3 lower 128x128 tiles) =======================
__global__ __launch_bounds__(256, 2) void syrk_kernel(const float* __restrict__ A)
{
    __shared__ float As[2][16][132];
    __shared__ float Bs[2][16][132];
    int t = blockIdx.x, b = blockIdx.y;
    int ti = (t == 0) ? 0 : 1;
    int tj = (t == 2) ? 1 : 0;

    const float* Abase = A + (size_t)b * (MDIM * VDIM);
    const float* Ai = Abase + (size_t)(ti * 128) * VDIM;
    const float* Aj = Abase + (size_t)(tj * 128) * VDIM;

    int tid = threadIdx.x;
    int tx = tid & 15, ty = tid >> 4;
    int lrow = tid >> 2, lf = tid & 3;

    float acc[8][8];
#pragma unroll
    for (int i = 0; i < 8; i++)
#pragma unroll
        for (int j = 0; j < 8; j++) acc[i][j] = 0.f;

    float4 pa0 = __ldcs((const float4*)&Ai[(size_t)lrow * VDIM + 4 * lf]);
    float4 pa1 = __ldcs((const float4*)&Ai[(size_t)(lrow + 64) * VDIM + 4 * lf]);
    float4 pb0 = __ldcs((const float4*)&Aj[(size_t)lrow * VDIM + 4 * lf]);
    float4 pb1 = __ldcs((const float4*)&Aj[(size_t)(lrow + 64) * VDIM + 4 * lf]);
    {
        float va[4] = {pa0.x, pa0.y, pa0.z, pa0.w};
        float vb[4] = {pa1.x, pa1.y, pa1.z, pa1.w};
        float vc[4] = {pb0.x, pb0.y, pb0.z, pb0.w};
        float vd[4] = {pb1.x, pb1.y, pb1.z, pb1.w};
#pragma unroll
        for (int c = 0; c < 4; c++) {
            As[0][4 * lf + c][lrow]      = va[c];
            As[0][4 * lf + c][lrow + 64] = vb[c];
            Bs[0][4 * lf + c][lrow]      = vc[c];
            Bs[0][4 * lf + c][lrow + 64] = vd[c];
        }
    }
    __syncthreads();

    int buf = 0;
    for (int kt = 0; kt < 64; kt++) {
        if (kt < 63) {
            int k0 = (kt + 1) * 16;
            pa0 = __ldcs((const float4*)&Ai[(size_t)lrow * VDIM + k0 + 4 * lf]);
            pa1 = __ldcs((const float4*)&Ai[(size_t)(lrow + 64) * VDIM + k0 + 4 * lf]);
            pb0 = __ldcs((const float4*)&Aj[(size_t)lrow * VDIM + k0 + 4 * lf]);
            pb1 = __ldcs((const float4*)&Aj[(size_t)(lrow + 64) * VDIM + k0 + 4 * lf]);
        }
#pragma unroll
        for (int kk = 0; kk < 16; kk++) {
            float4 alo = *(const float4*)&As[buf][kk][4 * ty];
            float4 ahi = *(const float4*)&As[buf][kk][64 + 4 * ty];
            float4 blo = *(const float4*)&Bs[buf][kk][4 * tx];
            float4 bhi = *(const float4*)&Bs[buf][kk][64 + 4 * tx];
            float ar[8] = {alo.x, alo.y, alo.z, alo.w, ahi.x, ahi.y, ahi.z, ahi.w};
            float br[8] = {blo.x, blo.y, blo.z, blo.w, bhi.x, bhi.y, bhi.z, bhi.w};
#pragma unroll
            for (int i = 0; i < 8; i++)
#pragma unroll
                for (int j = 0; j < 8; j++) acc[i][j] = fmaf(ar[i], br[j], acc[i][j]);
        }
        if (kt < 63) {
            int nb = buf ^ 1;
            float va[4] = {pa0.x, pa0.y, pa0.z, pa0.w};
            float vb[4] = {pa1.x, pa1.y, pa1.z, pa1.w};
            float vc[4] = {pb0.x, pb0.y, pb0.z, pb0.w};
            float vd[4] = {pb1.x, pb1.y, pb1.z, pb1.w};
#pragma unroll
            for (int c = 0; c < 4; c++) {
                As[nb][4 * lf + c][lrow]      = va[c];
                As[nb][4 * lf + c][lrow + 64] = vb[c];
                Bs[nb][4 * lf + c][lrow]      = vc[c];
                Bs[nb][4 * lf + c][lrow + 64] = vd[c];
            }
            __syncthreads();
            buf = nb;
        }
    }

    float* Gb = g_L + (size_t)b * (MDIM * MDIM);
#pragma unroll
    for (int rr = 0; rr < 8; rr++) {
        int rloc = (rr < 4) ? (4 * ty + rr) : (64 + 4 * ty + rr - 4);
        int grow = ti * 128 + rloc;
#pragma unroll
        for (int q = 0; q < 2; q++) {
            int cloc = 4 * tx + 64 * q;
            float4 v = make_float4(acc[rr][4 * q + 0], acc[rr][4 * q + 1],
                                   acc[rr][4 * q + 2], acc[rr][4 * q + 3]);
            if (ti == tj) {
                int d = rloc - cloc;
                if (d >= 0 && d < 4) ((float*)&v)[d] += JITTER;
            }
            *(float4*)&Gb[(size_t)grow * MDIM + tj * 128 + cloc] = v;
        }
    }
}

// ====== K2: per-batch Cholesky in packed SMEM + diag-block inverses + c = L^{-1} b ======
#define PIDX(i, j) ((i) * ((i) + 1) / 2 + (j))
__global__ __launch_bounds__(256) void chol_kernel(const float* __restrict__ b_in)
{
    extern __shared__ float sm2[];
    float* P    = sm2;
    float* Inv  = sm2 + 32896;
    float* tst  = Inv + 4 * 64 * 65;
    float* cvec = tst + 64;
    float* colk = cvec + 256;

    int b = blockIdx.x, tid = threadIdx.x;
    int w = tid >> 5, lane = tid & 31;
    const float* Gb = g_L + (size_t)b * (MDIM * MDIM);

    {
        int i = tid, base = PIDX(i, 0);
        for (int j = 0; j <= i; j++) P[base + j] = Gb[i * MDIM + j];
    }
    __syncthreads();

    for (int k = 0; k < MDIM; k++) {
        if (tid == 0) P[PIDX(k, k)] = sqrtf(P[PIDX(k, k)]);
        __syncthreads();
        float dk = P[PIDX(k, k)];
        if (tid > k) {
            float v = P[PIDX(tid, 0) + k] / dk;
            P[PIDX(tid, 0) + k] = v;
            colk[tid] = v;
        }
        __syncthreads();
        for (int i = k + 1 + w; i < MDIM; i += 8) {
            float lik = colk[i];
            int base = PIDX(i, 0);
            for (int j = k + 1 + lane; j <= i; j += 32)
                P[base + j] = fmaf(-lik, colk[j], P[base + j]);
        }
        __syncthreads();
    }

    {
        int blk = tid >> 6, col = tid & 63, b0 = blk * 64;
        float* Ib = Inv + blk * 64 * 65;
        for (int i = 0; i < col; i++) Ib[i * 65 + col] = 0.f;
        for (int i = col; i < 64; i++) {
            int gi = b0 + i, gbase = PIDX(gi, 0);
            float s = (i == col) ? 1.f : 0.f;
            for (int k = col; k < i; k++) s = fmaf(-P[gbase + b0 + k], Ib[k * 65 + col], s);
            Ib[i * 65 + col] = s / P[gbase + gi];
        }
    }
    __syncthreads();

    {
        const float* bv = b_in + (size_t)b * MDIM;
        for (int blk = 0; blk < 4; blk++) {
            if (tid < 64) {
                int gi = blk * 64 + tid, gb = PIDX(gi, 0);
                float s = bv[gi];
                for (int j = 0; j < blk * 64; j++) s = fmaf(-P[gb + j], cvec[j], s);
                tst[tid] = s;
            }
            __syncthreads();
            if (tid < 64) {
                const float* Ib = Inv + blk * 64 * 65 + tid * 65;
                float s = 0.f;
                for (int k = 0; k < 64; k++) s = fmaf(Ib[k], tst[k], s);
                cvec[blk * 64 + tid] = s;
            }
            __syncthreads();
        }
    }

    {
        int i = tid, base = PIDX(i, 0);
        float* Lo = g_L + (size_t)b * (MDIM * MDIM) + i * MDIM;
        for (int j = 0; j <= i; j++) Lo[j] = P[base + j];

        int blk = tid >> 6, r = tid & 63;
        const float* Ib = Inv + blk * 64 * 65 + r * 65;
        float* o = g_Ldi + (((size_t)b * 4 + blk) * 64 + r) * 64;
        for (int k = 0; k < 64; k++) o[k] = Ib[k];

        g_c[(size_t)b * MDIM + tid] = cvec[tid];
    }
}

// =================== K3: W = L^{-1} A  (blocked trsm; writes fp32 + fp16 copies) ===================
__global__ __launch_bounds__(256, 2) void trsm_kernel(const float* __restrict__ A)
{
    extern __shared__ float sm3[];
    float* Tp = sm3;             // [64][132]
    float* Lb = sm3 + 8448;      // [2][16][68]
    float* Wt = Lb + 2176;       // [2][16][132]
    float* Db = sm3 + 8448;      // [64][68]  (overlaps Lb/Wt)

    int vt = blockIdx.x, b = blockIdx.y;
    int vc = vt * 128;
    int tid = threadIdx.x, tx = tid & 15, ty = tid >> 4;
    const float* Ab = A + (size_t)b * (MDIM * VDIM);
    const float* Lg = g_L + (size_t)b * (MDIM * MDIM);
    float* Wg = g_W + (size_t)b * (MDIM * VDIM);
    __half* Wh = g_Wh + (size_t)b * (MDIM * VDIM);

    int r4 = tid >> 2, f4 = tid & 3;
    int kkA = tid >> 5, cg = tid & 31;

    for (int i = 0; i < 4; i++) {
        float acc[4][8];
#pragma unroll
        for (int r = 0; r < 4; r++)
#pragma unroll
            for (int q = 0; q < 2; q++) {
                float4 av = __ldcs((const float4*)&Ab[(size_t)(i * 64 + 4 * ty + r) * VDIM + vc + 4 * tx + 64 * q]);
                acc[r][4 * q + 0] = av.x; acc[r][4 * q + 1] = av.y;
                acc[r][4 * q + 2] = av.z; acc[r][4 * q + 3] = av.w;
            }

        int nkt = 4 * i;
        if (nkt > 0) {
            float4 lv  = *(const float4*)&Lg[(size_t)(i * 64 + r4) * MDIM + 4 * f4];
            float4 wv0 = *(const float4*)&Wg[(size_t)(kkA)     * VDIM + vc + 4 * cg];
            float4 wv1 = *(const float4*)&Wg[(size_t)(kkA + 8) * VDIM + vc + 4 * cg];
            Lb[(4 * f4 + 0) * 68 + r4] = lv.x; Lb[(4 * f4 + 1) * 68 + r4] = lv.y;
            Lb[(4 * f4 + 2) * 68 + r4] = lv.z; Lb[(4 * f4 + 3) * 68 + r4] = lv.w;
            *(float4*)&Wt[kkA * 132 + 4 * cg] = wv0;
            *(float4*)&Wt[(kkA + 8) * 132 + 4 * cg] = wv1;
            __syncthreads();

            int buf = 0;
            for (int kt = 0; kt < nkt; kt++) {
                float4 lvn, wv0n, wv1n;
                if (kt + 1 < nkt) {
                    int k0 = (kt + 1) * 16;
                    lvn  = *(const float4*)&Lg[(size_t)(i * 64 + r4) * MDIM + k0 + 4 * f4];
                    wv0n = *(const float4*)&Wg[(size_t)(k0 + kkA)     * VDIM + vc + 4 * cg];
                    wv1n = *(const float4*)&Wg[(size_t)(k0 + kkA + 8) * VDIM + vc + 4 * cg];
                }
                const float* Lc = Lb + buf * 1088;
                const float* Wc = Wt + buf * 2112;
#pragma unroll
                for (int kk = 0; kk < 16; kk++) {
                    float4 a4 = *(const float4*)&Lc[kk * 68 + 4 * ty];
                    float4 w0 = *(const float4*)&Wc[kk * 132 + 4 * tx];
                    float4 w1 = *(const float4*)&Wc[kk * 132 + 64 + 4 * tx];
                    float ar[4] = {a4.x, a4.y, a4.z, a4.w};
                    float wv[8] = {w0.x, w0.y, w0.z, w0.w, w1.x, w1.y, w1.z, w1.w};
#pragma unroll
                    for (int r = 0; r < 4; r++)
#pragma unroll
                        for (int c = 0; c < 8; c++) acc[r][c] = fmaf(-ar[r], wv[c], acc[r][c]);
                }
                if (kt + 1 < nkt) {
                    int nb = buf ^ 1;
                    float* Ln = Lb + nb * 1088;
                    float* Wn = Wt + nb * 2112;
                    Ln[(4 * f4 + 0) * 68 + r4] = lvn.x; Ln[(4 * f4 + 1) * 68 + r4] = lvn.y;
                    Ln[(4 * f4 + 2) * 68 + r4] = lvn.z; Ln[(4 * f4 + 3) * 68 + r4] = lvn.w;
                    *(float4*)&Wn[kkA * 132 + 4 * cg] = wv0n;
                    *(float4*)&Wn[(kkA + 8) * 132 + 4 * cg] = wv1n;
                    __syncthreads();
                    buf = nb;
                }
            }
            __syncthreads();
        }

#pragma unroll
        for (int r = 0; r < 4; r++)
#pragma unroll
            for (int q = 0; q < 2; q++) {
                float4 o = make_float4(acc[r][4 * q + 0], acc[r][4 * q + 1],
                                       acc[r][4 * q + 2], acc[r][4 * q + 3]);
                *(float4*)&Tp[(4 * ty + r) * 132 + 4 * tx + 64 * q] = o;
            }
#pragma unroll
        for (int s = 0; s < 4; s++) {
            int n = tid + 256 * s;
            int r = n >> 4, f = n & 15;
            float4 dv = *(const float4*)&g_Ldi[(((size_t)b * 4 + i) * 64 + r) * 64 + 4 * f];
            Db[(4 * f + 0) * 68 + r] = dv.x; Db[(4 * f + 1) * 68 + r] = dv.y;
            Db[(4 * f + 2) * 68 + r] = dv.z; Db[(4 * f + 3) * 68 + r] = dv.w;
        }
        __syncthreads();

        float acc2[4][8];
#pragma unroll
        for (int r = 0; r < 4; r++)
#pragma unroll
            for (int c = 0; c < 8; c++) acc2[r][c] = 0.f;
#pragma unroll 16
        for (int kk = 0; kk < 64; kk++) {
            float4 a4 = *(const float4*)&Db[kk * 68 + 4 * ty];
            float4 t0 = *(const float4*)&Tp[kk * 132 + 4 * tx];
            float4 t1 = *(const float4*)&Tp[kk * 132 + 64 + 4 * tx];
            float ar[4] = {a4.x, a4.y, a4.z, a4.w};
            float tv[8] = {t0.x, t0.y, t0.z, t0.w, t1.x, t1.y, t1.z, t1.w};
#pragma unroll
            for (int r = 0; r < 4; r++)
#pragma unroll
                for (int c = 0; c < 8; c++) acc2[r][c] = fmaf(ar[r], tv[c], acc2[r][c]);
        }

#pragma unroll
        for (int r = 0; r < 4; r++)
#pragma unroll
            for (int q = 0; q < 2; q++) {
                float4 o = make_float4(acc2[r][4 * q + 0], acc2[r][4 * q + 1],
                                       acc2[r][4 * q + 2], acc2[r][4 * q + 3]);
                size_t off = (size_t)(i * 64 + 4 * ty + r) * VDIM + vc + 4 * tx + 64 * q;
                *(float4*)&Wg[off] = o;
                __half2 h01 = __floats2half2_rn(o.x, o.y);
                __half2 h23 = __floats2half2_rn(o.z, o.w);
                __half2 hh[2] = {h01, h23};
                *(uint2*)&Wh[off] = *(uint2*)hh;
            }
        __syncthreads();
    }
}

// =================== K5: fused ADMM loop (cp.async ring pipeline on fp16 W) ===================
__device__ __forceinline__ void cp_async16(void* smem_dst, const void* gmem_src)
{
    unsigned dst = (unsigned)__cvta_generic_to_shared(smem_dst);
    asm volatile("cp.async.cg.shared.global [%0], [%1], 16;"
                 :: "r"(dst), "l"(gmem_src) : "memory");
}

__global__ __launch_bounds__(256, 2) void admm_kernel(
    const float* __restrict__ x_in, const int* __restrict__ mask,
    float* __restrict__ out)
{
    extern __shared__ __align__(16) unsigned char smraw[];
    float* rsh = (float*)smraw;
    float* vp  = rsh + 1024;
    float* cc  = rsh + 9216;
    __half* ring = (__half*)(smraw + 37888);

    int b = blockIdx.x, tid = threadIdx.x;
    int w = tid >> 5, lane = tid & 31;
    const __half* Whb = g_Wh + (size_t)b * (MDIM * VDIM);
    const float*  Wfb = g_W  + (size_t)b * (MDIM * VDIM);
    __half* ringw = ring + w * (RING_SLOTS * 1024);

#pragma unroll
    for (int r = 0; r < 3; r++) {
        const __half* grow = Whb + (size_t)(w * 32 + r) * VDIM;
        __half* slot = ringw + r * 1024;
#pragma unroll
        for (int q = 0; q < 4; q++) {
            int ch = lane + 32 * q;
            cp_async16(slot + ch * 8, grow + ch * 8);
        }
        asm volatile("cp.async.commit_group;" ::: "memory");
    }

    float4 xreg = *(const float4*)&x_in[(size_t)b * VDIM + 4 * tid];
    int4 m4 = *(const int4*)&mask[4 * tid];
    float4 ureg = make_float4(0.f, 0.f, 0.f, 0.f);
    float4 rown = xreg;
    cc[tid] = g_c[(size_t)b * MDIM + tid];
    *(float4*)&rsh[4 * tid] = xreg;

    for (int it = 0; it < 100; it++) {
        __syncthreads();
        float rr[32];
#pragma unroll
        for (int q = 0; q < 4; q++) {
            float4 r0 = *(float4*)&rsh[256 * q + 8 * lane];
            float4 r1 = *(float4*)&rsh[256 * q + 8 * lane + 4];
            rr[8 * q + 0] = r0.x; rr[8 * q + 1] = r0.y; rr[8 * q + 2] = r0.z; rr[8 * q + 3] = r0.w;
            rr[8 * q + 4] = r1.x; rr[8 * q + 5] = r1.y; rr[8 * q + 6] = r1.z; rr[8 * q + 7] = r1.w;
        }
        float v[32];
#pragma unroll
        for (int c = 0; c < 32; c++) v[c] = 0.f;

        for (int j = 0; j < 32; j++) {
            {
                int pr = (j + 3) & 31;
                const __half* grow = Whb + (size_t)(w * 32 + pr) * VDIM;
                __half* slot = ringw + ((j + 3) & 3) * 1024;
#pragma unroll
                for (int q = 0; q < 4; q++) {
                    int ch = lane + 32 * q;
                    cp_async16(slot + ch * 8, grow + ch * 8);
                }
                asm volatile("cp.async.commit_group;" ::: "memory");
            }
            asm volatile("cp.async.wait_group 3;" ::: "memory");

            const __half* slot = ringw + (j & 3) * 1024;
            float s = 0.f;
#pragma unroll
            for (int q = 0; q < 4; q++) {
                uint4 u = *(const uint4*)(slot + (lane + 32 * q) * 8);
                float2 f0 = __half22float2(*(__half2*)&u.x);
                float2 f1 = __half22float2(*(__half2*)&u.y);
                float2 f2 = __half22float2(*(__half2*)&u.z);
                float2 f3 = __half22float2(*(__half2*)&u.w);
                s = fmaf(f0.x, rr[8 * q + 0], s); s = fmaf(f0.y, rr[8 * q + 1], s);
                s = fmaf(f1.x, rr[8 * q + 2], s); s = fmaf(f1.y, rr[8 * q + 3], s);
                s = fmaf(f2.x, rr[8 * q + 4], s); s = fmaf(f2.y, rr[8 * q + 5], s);
                s = fmaf(f3.x, rr[8 * q + 6], s); s = fmaf(f3.y, rr[8 * q + 7], s);
            }
#pragma unroll
            for (int off = 16; off > 0; off >>= 1) s += __shfl_xor_sync(0xffffffffu, s, off);
            float coef = 0.5f * s - cc[(w << 5) + j];
#pragma unroll
            for (int q = 0; q < 4; q++) {
                uint4 u = *(const uint4*)(slot + (lane + 32 * q) * 8);
                float2 f0 = __half22float2(*(__half2*)&u.x);
                float2 f1 = __half22float2(*(__half2*)&u.y);
                float2 f2 = __half22float2(*(__half2*)&u.z);
                float2 f3 = __half22float2(*(__half2*)&u.w);
                v[8 * q + 0] = fmaf(coef, f0.x, v[8 * q + 0]); v[8 * q + 1] = fmaf(coef, f0.y, v[8 * q + 1]);
                v[8 * q + 2] = fmaf(coef, f1.x, v[8 * q + 2]); v[8 * q + 3] = fmaf(coef, f1.y, v[8 * q + 3]);
                v[8 * q + 4] = fmaf(coef, f2.x, v[8 * q + 4]); v[8 * q + 5] = fmaf(coef, f2.y, v[8 * q + 5]);
                v[8 * q + 6] = fmaf(coef, f3.x, v[8 * q + 6]); v[8 * q + 7] = fmaf(coef, f3.y, v[8 * q + 7]);
            }
        }
#pragma unroll
        for (int q = 0; q < 4; q++) {
            *(float4*)&vp[w * 1024 + 256 * q + 8 * lane]     = make_float4(v[8 * q + 0], v[8 * q + 1], v[8 * q + 2], v[8 * q + 3]);
            *(float4*)&vp[w * 1024 + 256 * q + 8 * lane + 4] = make_float4(v[8 * q + 4], v[8 * q + 5], v[8 * q + 6], v[8 * q + 7]);
        }
        __syncthreads();

        float4 vs = make_float4(0.f, 0.f, 0.f, 0.f);
#pragma unroll
        for (int ww = 0; ww < 8; ww++) {
            float4 p = *(float4*)&vp[ww * 1024 + 4 * tid];
            vs.x += p.x; vs.y += p.y; vs.z += p.z; vs.w += p.w;
        }
        float4 xk;
        xk.x = 0.5f * rown.x - vs.x;
        xk.y = 0.5f * rown.y - vs.y;
        xk.z = 0.5f * rown.z - vs.z;
        xk.w = 0.5f * rown.w - vs.w;

        float wv, zv;
        wv = xk.x + ureg.x; zv = (m4.x > 0) ? fminf(wv, 0.f) : wv; ureg.x = wv - zv; rown.x = xreg.x + zv - ureg.x;
        wv = xk.y + ureg.y; zv = (m4.y > 0) ? fminf(wv, 0.f) : wv; ureg.y = wv - zv; rown.y = xreg.y + zv - ureg.y;
        wv = xk.z + ureg.z; zv = (m4.z > 0) ? fminf(wv, 0.f) : wv; ureg.z = wv - zv; rown.z = xreg.z + zv - ureg.z;
        wv = xk.w + ureg.w; zv = (m4.w > 0) ? fminf(wv, 0.f) : wv; ureg.w = wv - zv; rown.w = xreg.w + zv - ureg.w;
        *(float4*)&rsh[4 * tid] = rown;
    }

    asm volatile("cp.async.wait_group 0;" ::: "memory");

    __syncthreads();
    {
        float rr[32];
#pragma unroll
        for (int q = 0; q < 4; q++) {
            float4 r0 = *(float4*)&rsh[256 * q + 8 * lane];
            float4 r1 = *(float4*)&rsh[256 * q + 8 * lane + 4];
            rr[8 * q + 0] = r0.x; rr[8 * q + 1] = r0.y; rr[8 * q + 2] = r0.z; rr[8 * q + 3] = r0.w;
            rr[8 * q + 4] = r1.x; rr[8 * q + 5] = r1.y; rr[8 * q + 6] = r1.z; rr[8 * q + 7] = r1.w;
        }
        float v[32];
#pragma unroll
        for (int c = 0; c < 32; c++) v[c] = 0.f;

        for (int j = 0; j < 32; j++) {
            int m = (w << 5) + j;
            const float4* row = (const float4*)(Wfb + (size_t)m * VDIM);
            float af[32];
#pragma unroll
            for (int q = 0; q < 4; q++) {
                float4 a0 = __ldcs(&row[2 * (lane + 32 * q)]);
                float4 a1 = __ldcs(&row[2 * (lane + 32 * q) + 1]);
                af[8 * q + 0] = a0.x; af[8 * q + 1] = a0.y; af[8 * q + 2] = a0.z; af[8 * q + 3] = a0.w;
                af[8 * q + 4] = a1.x; af[8 * q + 5] = a1.y; af[8 * q + 6] = a1.z; af[8 * q + 7] = a1.w;
            }
            float s = 0.f;
#pragma unroll
            for (int c = 0; c < 32; c++) s = fmaf(af[c], rr[c], s);
#pragma unroll
            for (int off = 16; off > 0; off >>= 1) s += __shfl_xor_sync(0xffffffffu, s, off);
            float coef = 0.5f * s - cc[m];
#pragma unroll
            for (int c = 0; c < 32; c++) v[c] = fmaf(coef, af[c], v[c]);
        }
#pragma unroll
        for (int q = 0; q < 4; q++) {
            *(float4*)&vp[w * 1024 + 256 * q + 8 * lane]     = make_float4(v[8 * q + 0], v[8 * q + 1], v[8 * q + 2], v[8 * q + 3]);
            *(float4*)&vp[w * 1024 + 256 * q + 8 * lane + 4] = make_float4(v[8 * q + 4], v[8 * q + 5], v[8 * q + 6], v[8 * q + 7]);
        }
        __syncthreads();

        float4 vs = make_float4(0.f, 0.f, 0.f, 0.f);
#pragma unroll
        for (int ww = 0; ww < 8; ww++) {
            float4 p = *(float4*)&vp[ww * 1024 + 4 * tid];
            vs.x += p.x; vs.y += p.y; vs.z += p.z; vs.w += p.w;
        }
        float4 xk;
        xk.x = 0.5f * rown.x - vs.x;
        xk.y = 0.5f * rown.y - vs.y;
        xk.z = 0.5f * rown.z - vs.z;
        xk.w = 0.5f * rown.w - vs.w;
        *(float4*)&out[(size_t)b * VDIM + 4 * tid] = xk;
    }
}

// ======================================= launch =======================================
extern "C" void kernel_launch(void* const* d_in, const int* in_sizes, int n_in,
                              void* d_out, int out_size)
{
    (void)in_sizes; (void)n_in; (void)out_size;
    const float* x    = (const float*)d_in[0];
    const float* bvec = (const float*)d_in[1];
    const float* A    = (const float*)d_in[2];
    const int*   mask = (const int*)d_in[3];
    float* out = (float*)d_out;

    size_t chol_smem = (size_t)(32896 + 4 * 64 * 65 + 64 + 256 + 256) * sizeof(float);
    size_t trsm_smem = (size_t)(8448 + 2176 + 4224) * sizeof(float);
    size_t admm_smem = (size_t)37888 + (size_t)8 * RING_SLOTS * 1024 * sizeof(__half);

    cudaFuncSetAttribute((const void*)chol_kernel, cudaFuncAttributeMaxDynamicSharedMemorySize, (int)chol_smem);
    cudaFuncSetAttribute((const void*)trsm_kernel, cudaFuncAttributeMaxDynamicSharedMemorySize, (int)trsm_smem);
    cudaFuncSetAttribute((const void*)admm_kernel, cudaFuncAttributeMaxDynamicSharedMemorySize, (int)admm_smem);

    syrk_kernel<<<dim3(3, BATCH), 256>>>(A);
    chol_kernel<<<BATCH, 256, chol_smem>>>(bvec);
    trsm_kernel<<<dim3(8, BATCH), 256, trsm_smem>>>(A);
    admm_kernel<<<BATCH, 256, admm_smem>>>(x, mask, out);
}